// round 12
// baseline (speedup 1.0000x reference)
#include <cuda_runtime.h>
#include <cuda_bf16.h>
#include <cstdint>

// f_z[b,i] = z[b,i] + sum_{j<i} h[b, i*(i-1)/2 + j] * z[b,j]
// R11 insight: pairing rows (i, 513-i) gives both rows the SAME off%4 class,
// so z in registers (from shifted smem copies) serves every h-quad with the
// lane's own regs -- no per-quad LDS, no shfl. R12: split loads/consume into
// two waves so max live h-quads = 4 (regs 63 -> ~48) and cap 5 CTAs/SM to
// recover occupancy lost in R11.

#define DIM 512
#define HLEN ((DIM * (DIM - 1)) / 2)   // 130816
#define THREADS 256
#define ZPADF 640
#define FULL 0xffffffffu

// ia: short row (2..257, 3 steps). ib: long row (256..511, 5 steps).
// Precondition: off(ia)%4 == off(ib)%4.
__device__ __forceinline__ void do_pair(
    const float* __restrict__ hbase, const float* __restrict__ zsh,
    float* __restrict__ ob, int ia, int ib, int lane)
{
    const unsigned offa = (unsigned)(ia * (ia - 1) / 2);
    const unsigned offb = (unsigned)(ib * (ib - 1) / 2);
    const int m = (int)(offa & 3u);            // == offb & 3

    const float4* ha4 = (const float4*)(hbase + (offa & ~3u));
    const float4* hb4 = (const float4*)(hbase + (offb & ~3u));

    const int ea = ia + m, eb = ib + m;        // valid padded elems: [m, e)
    const int nqa = (ea + 3) >> 2;             // <= 65
    const int nqb = (eb + 3) >> 2;             // 64..129
    const int vba = ea >> 2, ca = ea & 3;      // a-boundary: step 0..2
    const int vbb = eb >> 2, cb = eb & 3;      // b-boundary: step 2..4

    const float4* Zm4 = (const float4*)(zsh + m * ZPADF);
    const float4 zf = make_float4(0.f, 0.f, 0.f, 0.f);

    float s0 = 0.f, s1 = 0.f, s2 = 0.f, s3 = 0.f;
    #define STEP(Q, ZV) {                                       \
        s0 = fmaf(Q.x, ZV.x, s0);                               \
        s1 = fmaf(Q.y, ZV.y, s1);                               \
        s2 = fmaf(Q.z, ZV.z, s2);                               \
        s3 = fmaf(Q.w, ZV.w, s3);                               \
    }
    #define JUNK(Q, ZV, c, acc) {                               \
        float jnk = Q.w * ZV.w;                                 \
        if ((c) <= 2) jnk = fmaf(Q.z, ZV.z, jnk);               \
        if ((c) <= 1) jnk = fmaf(Q.y, ZV.y, jnk);               \
        acc -= jnk;                                             \
    }

    // ---------- wave 1: B0..B3 ----------
    {
        float4 B0 = __ldcs(hb4 + lane);            // nqb >= 64: always full
        float4 B1 = __ldcs(hb4 + lane + 32);
        float4 B2 = (lane + 64 < nqb) ? __ldcs(hb4 + lane + 64) : zf;
        float4 B3 = (lane + 96 < nqb) ? __ldcs(hb4 + lane + 96) : zf;
        float4 zq0 = Zm4[lane];
        float4 zq1 = Zm4[lane + 32];
        float4 zq2 = Zm4[lane + 64];
        float4 zq3 = Zm4[lane + 96];
        STEP(B0, zq0) STEP(B1, zq1) STEP(B2, zq2) STEP(B3, zq3)
        if (cb && (vbb >> 5) == 2 && lane == (vbb & 31)) JUNK(B2, zq2, cb, s0)
        if (cb && (vbb >> 5) == 3 && lane == (vbb & 31)) JUNK(B3, zq3, cb, s0)
    }
    float sumb_part = s0;   // carry partial via s0 chain

    // ---------- wave 2: B4 + A0..A2 ----------
    float suma, sumb;
    {
        float4 B4 = (lane + 128 < nqb) ? __ldcs(hb4 + lane + 128) : zf;
        float4 A0 = (lane       < nqa) ? __ldcs(ha4 + lane)       : zf;
        float4 A1 = (lane + 32  < nqa) ? __ldcs(ha4 + lane + 32)  : zf;
        float4 A2 = (lane + 64  < nqa) ? __ldcs(ha4 + lane + 64)  : zf;
        float4 zq0 = Zm4[lane];
        float4 zq1 = Zm4[lane + 32];
        float4 zq2 = Zm4[lane + 64];
        float4 zq4 = Zm4[lane + 128];

        STEP(B4, zq4)
        if (cb && (vbb >> 5) == 4 && lane == (vbb & 31)) JUNK(B4, zq4, cb, s0)
        sumb = (s0 + s1) + (s2 + s3);

        s0 = s1 = s2 = s3 = 0.f;
        STEP(A0, zq0) STEP(A1, zq1) STEP(A2, zq2)
        if (ca && lane == (vba & 31)) {
            const int st = vba >> 5;               // 0..2
            float4 Q  = (st == 0) ? A0  : (st == 1) ? A1  : A2;
            float4 ZV = (st == 0) ? zq0 : (st == 1) ? zq1 : zq2;
            JUNK(Q, ZV, ca, s0)
        }
        suma = (s0 + s1) + (s2 + s3);
    }
    #undef STEP
    #undef JUNK
    (void)sumb_part;

    #pragma unroll
    for (int o = 16; o; o >>= 1) {
        suma += __shfl_xor_sync(FULL, suma, o);
        sumb += __shfl_xor_sync(FULL, sumb, o);
    }

    if (lane == 0) {
        ob[ia] = zsh[ia] + suma;    // Z_0 is plain z
        ob[ib] = zsh[ib] + sumb;
    }
}

__device__ __forceinline__ void do_work(
    const float* __restrict__ hbase, const float* __restrict__ zsh,
    float* __restrict__ ob, int w, int lane)
{
    if (w >= 2)      do_pair(hbase, zsh, ob, w, 513 - w, lane);
    else if (w == 1) do_pair(hbase, zsh, ob, 257, 256, lane);
    else if (lane == 0) {                      // rows 0, 1
        ob[0] = zsh[0];
        ob[1] = zsh[1] + hbase[0] * zsh[0];
    }
}

__global__ __launch_bounds__(THREADS, 5) void LinearMap_kernel(
    const float* __restrict__ z,
    const float* __restrict__ h,
    float* __restrict__ out,
    int out_size)
{
    __shared__ float zsh[4 * ZPADF];    // shifted copy m at m*ZPADF

    const int b    = blockIdx.x >> 4;   // / 16
    const int cg   = blockIdx.x & 15;
    const int tid  = threadIdx.x;
    const int warp = tid >> 5;
    const int lane = tid & 31;

    // zero pad regions ([512,640) per copy; heads [0,m))
    {
        int m = tid >> 6;               // 0..3
        int j = 512 + (tid & 63);
        zsh[m * ZPADF + j]      = 0.f;
        zsh[m * ZPADF + j + 64] = 0.f;
        if (tid < 16) {
            int mm = tid >> 2, k = tid & 3;
            if (k < mm) zsh[mm * ZPADF + k] = 0.f;
        }
    }
    __syncthreads();
    // data into all 4 shifted copies: Z_m[j+m] = z[j]
    {
        const float* zb = z + (size_t)b * DIM;
        #pragma unroll
        for (int j = tid; j < DIM; j += THREADS) {
            float v = zb[j];
            zsh[j]                 = v;
            zsh[ZPADF     + j + 1] = v;
            zsh[2 * ZPADF + j + 2] = v;
            zsh[3 * ZPADF + j + 3] = v;
        }
    }
    __syncthreads();

    const float* hbase = h + (size_t)b * HLEN;
    float* ob = out + (size_t)b * DIM;
    const int base = cg * 16;                   // 16 work units per CTA

    do_work(hbase, zsh, ob, base + warp,     lane);
    do_work(hbase, zsh, ob, base + 8 + warp, lane);

    // logdet / tail zeroing (d_out is poisoned)
    if (blockIdx.x == 0) {
        const int nfz = (int)(gridDim.x >> 4) * DIM;
        for (int k = nfz + tid; k < out_size; k += THREADS) out[k] = 0.0f;
    }
}

extern "C" void kernel_launch(void* const* d_in, const int* in_sizes, int n_in,
                              void* d_out, int out_size)
{
    const float* z = (const float*)d_in[0];   // [batch, 512]
    const float* h = (const float*)d_in[1];   // [batch, 130816]
    float* out = (float*)d_out;

    const int batch = in_sizes[0] / DIM;      // 256

    dim3 grid(batch * 16);                    // 4096 identical CTAs
    LinearMap_kernel<<<grid, THREADS>>>(z, h, out, out_size);
}